// round 8
// baseline (speedup 1.0000x reference)
#include <cuda_runtime.h>
#include <cuda_bf16.h>

#define NB 64      // batch
#define TT 512     // timesteps
#define DD 512     // input size
#define HH 512     // hidden size

#define GROUPS 4           // m-groups (16 batch rows each) -- independent recurrences
#define SUBS 32            // n-CTAs per group
#define SCAN_CTAS 64       // 2 pairs x 32 subs; each CTA runs TWO groups interleaved
#define SCAN_NT 16         // hidden columns per CTA
#define MROWS 16           // batch rows per group
#define HSTRIDE 520        // 512 + 8 pad halves (16B-aligned rows, conflict-free LDSM)

// ---------------- scratch (device globals; no allocation allowed) ----------
__device__ __align__(16) __nv_bfloat16 g_hh[2][NB * HH];  // h hi, double buffered
__device__ __align__(16) __nv_bfloat16 g_hl[2][NB * HH];  // h lo
__device__ __align__(128) unsigned g_cnt[GROUPS * 32];    // monotonic arrival counters

// ---------------- helpers --------------------------------------------------
__device__ __forceinline__ void split2(float v, __nv_bfloat16 &hi, __nv_bfloat16 &lo) {
    hi = __float2bfloat16(v);
    lo = __float2bfloat16(v - __bfloat162float(hi));
}

__device__ __forceinline__ void mma4(float *c, unsigned a0, unsigned a1, unsigned a2,
                                     unsigned a3, unsigned b0, unsigned b1) {
    asm volatile(
        "mma.sync.aligned.m16n8k16.row.col.f32.bf16.bf16.f32 "
        "{%0,%1,%2,%3}, {%4,%5,%6,%7}, {%8,%9}, {%0,%1,%2,%3};\n"
        : "+f"(c[0]), "+f"(c[1]), "+f"(c[2]), "+f"(c[3])
        : "r"(a0), "r"(a1), "r"(a2), "r"(a3), "r"(b0), "r"(b1));
}

__device__ __forceinline__ void ldsm_x4(unsigned &r0, unsigned &r1, unsigned &r2,
                                        unsigned &r3, unsigned addr) {
    asm volatile("ldmatrix.sync.aligned.m8n8.x4.shared.b16 {%0,%1,%2,%3}, [%4];"
                 : "=r"(r0), "=r"(r1), "=r"(r2), "=r"(r3)
                 : "r"(addr));
}

__device__ __forceinline__ void cp16(void *dst_smem, const void *src) {
    unsigned d = (unsigned)__cvta_generic_to_shared(dst_smem);
    asm volatile("cp.async.cg.shared.global [%0], [%1], 16;" :: "r"(d), "l"(src));
}

__device__ __forceinline__ float fast_tanh(float x) {
    float e = __expf(2.0f * x);
    return 1.0f - __fdividef(2.0f, e + 1.0f);
}

__device__ __forceinline__ unsigned pack2(__nv_bfloat16 a, __nv_bfloat16 b) {
    __nv_bfloat162 p = {a, b};
    return *(unsigned *)&p;
}

// ---------------- kernel 1: xWx = x @ Wx + b  -> out (R5 version) ----------
__global__ __launch_bounds__(256) void gemm_xwx_kernel(
    const float *__restrict__ x, const float *__restrict__ Wx,
    const float *__restrict__ b, float *__restrict__ out) {

    __shared__ __align__(16) __nv_bfloat16 Ah[128 * 40];
    __shared__ __align__(16) __nv_bfloat16 Al[128 * 40];
    __shared__ __align__(16) __nv_bfloat16 Bh[64 * 40];
    __shared__ __align__(16) __nv_bfloat16 Bl[64 * 40];

    const int tid  = threadIdx.x;
    const int warp = tid >> 5;
    const int lane = tid & 31;
    const int g    = lane >> 2;
    const int tg   = lane & 3;
    const int wm   = warp >> 1;
    const int wn   = warp & 1;
    const int row0 = blockIdx.x * 128;
    const int col0 = blockIdx.y * 64;

    const int quad = lane >> 3, lrow = lane & 7;
    unsigned aHaddr[2], aLaddr[2], bAddr[4];
#pragma unroll
    for (int mt = 0; mt < 2; mt++) {
        int r = wm * 32 + mt * 16 + (quad & 1) * 8 + lrow;
        int off = r * 40 + (quad >> 1) * 8;
        aHaddr[mt] = (unsigned)__cvta_generic_to_shared(Ah + off);
        aLaddr[mt] = (unsigned)__cvta_generic_to_shared(Al + off);
    }
#pragma unroll
    for (int nt = 0; nt < 4; nt++) {
        int r = wn * 32 + nt * 8 + lrow;
        const __nv_bfloat16 *base = (quad < 2) ? Bh : Bl;
        bAddr[nt] = (unsigned)__cvta_generic_to_shared(base + r * 40 + (quad & 1) * 8);
    }

    float acc[2][4][4];
#pragma unroll
    for (int mt = 0; mt < 2; mt++)
#pragma unroll
        for (int nt = 0; nt < 4; nt++)
#pragma unroll
            for (int i = 0; i < 4; i++) acc[mt][nt][i] = 0.0f;

    for (int k0 = 0; k0 < DD; k0 += 32) {
        __syncthreads();
#pragma unroll
        for (int i = 0; i < 16; i++) {
            int idx = tid + i * 256;
            int r = idx >> 5, c = idx & 31;
            float v = x[(size_t)(row0 + r) * DD + k0 + c];
            __nv_bfloat16 hi, lo; split2(v, hi, lo);
            Ah[r * 40 + c] = hi; Al[r * 40 + c] = lo;
        }
#pragma unroll
        for (int i = 0; i < 8; i++) {
            int idx = tid + i * 256;
            int nn = idx & 63, kk = idx >> 6;
            float v = Wx[(size_t)(k0 + kk) * HH + col0 + nn];
            __nv_bfloat16 hi, lo; split2(v, hi, lo);
            Bh[nn * 40 + kk] = hi; Bl[nn * 40 + kk] = lo;
        }
        __syncthreads();

#pragma unroll
        for (int ks = 0; ks < 2; ks++) {
            const unsigned off = ks * 32;
            unsigned bfr[4][4];
#pragma unroll
            for (int nt = 0; nt < 4; nt++)
                ldsm_x4(bfr[nt][0], bfr[nt][1], bfr[nt][2], bfr[nt][3], bAddr[nt] + off);
#pragma unroll
            for (int mt = 0; mt < 2; mt++) {
                unsigned a0, a1, a2, a3, l0, l1, l2, l3;
                ldsm_x4(a0, a1, a2, a3, aHaddr[mt] + off);
                ldsm_x4(l0, l1, l2, l3, aLaddr[mt] + off);
#pragma unroll
                for (int nt = 0; nt < 4; nt++) {
                    mma4(acc[mt][nt], a0, a1, a2, a3, bfr[nt][0], bfr[nt][1]);
                    mma4(acc[mt][nt], a0, a1, a2, a3, bfr[nt][2], bfr[nt][3]);
                    mma4(acc[mt][nt], l0, l1, l2, l3, bfr[nt][0], bfr[nt][1]);
                }
            }
        }
    }

#pragma unroll
    for (int mt = 0; mt < 2; mt++)
#pragma unroll
        for (int nt = 0; nt < 4; nt++) {
            int r = row0 + wm * 32 + mt * 16 + g;
            int c = col0 + wn * 32 + nt * 8 + tg * 2;
            float b0 = b[c], b1 = b[c + 1];
            out[(size_t)r * HH + c]           = acc[mt][nt][0] + b0;
            out[(size_t)r * HH + c + 1]       = acc[mt][nt][1] + b1;
            out[(size_t)(r + 8) * HH + c]     = acc[mt][nt][2] + b0;
            out[(size_t)(r + 8) * HH + c + 1] = acc[mt][nt][3] + b1;
        }
}

// ---------------- init: reset counters + pre-split h0 into buffer 1 --------
__global__ __launch_bounds__(128) void init_kernel(const float *__restrict__ h0) {
    const int idx = blockIdx.x * 128 + threadIdx.x;   // grid 64 -> 8192 float4
    float4 v = ((const float4 *)h0)[idx];
    __nv_bfloat16 hx, lx, hy, ly, hz, lz, hw, lw;
    split2(v.x, hx, lx); split2(v.y, hy, ly);
    split2(v.z, hz, lz); split2(v.w, hw, lw);
    ((uint2 *)g_hh[1])[idx] = make_uint2(pack2(hx, hy), pack2(hz, hw));
    ((uint2 *)g_hl[1])[idx] = make_uint2(pack2(lx, ly), pack2(lz, lw));
    if (blockIdx.x == 0 && threadIdx.x < GROUPS * 32) g_cnt[threadIdx.x] = 0;
}

// ---------------- kernel 2: persistent scan, 2 groups interleaved per CTA --
__global__ __launch_bounds__(256) void rnn_scan_kernel(
    const float *__restrict__ Wh, float *__restrict__ out) {

    extern __shared__ __nv_bfloat16 smem[];
    __nv_bfloat16 *Wsh = smem;                        // 16 x 520
    __nv_bfloat16 *Wsl = Wsh + SCAN_NT * HSTRIDE;     // 16 x 520
    __nv_bfloat16 *HhA = Wsl + SCAN_NT * HSTRIDE;     // 16 x 520
    __nv_bfloat16 *HlA = HhA + MROWS * HSTRIDE;
    __nv_bfloat16 *HhB = HlA + MROWS * HSTRIDE;
    __nv_bfloat16 *HlB = HhB + MROWS * HSTRIDE;
    __shared__ float redbuf[6 * 128];

    const int tid   = threadIdx.x;
    const int warp  = tid >> 5;
    const int lane  = tid & 31;
    const int g     = lane >> 2;
    const int tg    = lane & 3;
    const int pair  = blockIdx.x >> 5;      // 0: groups 0,1   1: groups 2,3
    const int sub   = blockIdx.x & 31;
    const int cb    = sub * SCAN_NT;
    const int grpA  = pair * 2, grpB = pair * 2 + 1;
    const int rbA   = grpA * MROWS, rbB = grpB * MROWS;
    const int kq    = warp >> 1;            // K-quarter 0..3
    const int ntile = warp & 1;             // n8 tile 0..1
    const int kb    = kq * 128;

    unsigned *cntA = &g_cnt[grpA * 32];
    unsigned *cntB = &g_cnt[grpB * 32];

    // resident Wh slice
    for (int idx = tid; idx < HH * SCAN_NT; idx += 256) {
        int n = idx & (SCAN_NT - 1), k = idx >> 4;
        float v = Wh[(size_t)k * HH + cb + n];
        __nv_bfloat16 hi, lo; split2(v, hi, lo);
        Wsh[n * HSTRIDE + k] = hi; Wsl[n * HSTRIDE + k] = lo;
    }

    // ldmatrix lane addresses
    const int quad = lane >> 3, lrow = lane & 7;
    const int aRow = (quad & 1) * 8 + lrow;
    const int aCol = kb + (quad >> 1) * 8;
    const unsigned adAhA = (unsigned)__cvta_generic_to_shared(HhA + aRow * HSTRIDE + aCol);
    const unsigned adAlA = (unsigned)__cvta_generic_to_shared(HlA + aRow * HSTRIDE + aCol);
    const unsigned adAhB = (unsigned)__cvta_generic_to_shared(HhB + aRow * HSTRIDE + aCol);
    const unsigned adAlB = (unsigned)__cvta_generic_to_shared(HlB + aRow * HSTRIDE + aCol);
    const __nv_bfloat16 *bbase = (quad < 2) ? Wsh : Wsl;
    const unsigned addrB = (unsigned)__cvta_generic_to_shared(
        bbase + (ntile * 8 + lrow) * HSTRIDE + kb + (quad & 1) * 8);

    const int ccol = cb + ntile * 8 + tg * 2;
    const int m0A = rbA + g, m1A = rbA + g + 8;
    const int m0B = rbB + g, m1B = rbB + g + 8;

    // staging for group X from published buffer sb (threads 64..255)
    auto stage192 = [&](__nv_bfloat16 *Hh, __nv_bfloat16 *Hl, int rb, int sb) {
        const __nv_bfloat16 *sH = g_hh[sb] + (size_t)rb * HH;
        const __nv_bfloat16 *sL = g_hl[sb] + (size_t)rb * HH;
        for (int c = tid - 64; c < 2048; c += 192) {
            int bufsel = c >> 10, cc = c & 1023;
            int r = cc >> 6, col = (cc & 63) * 8;
            if (bufsel == 0) cp16(Hh + r * HSTRIDE + col, sH + r * HH + col);
            else             cp16(Hl + r * HSTRIDE + col, sL + r * HH + col);
        }
        asm volatile("cp.async.commit_group;");
        asm volatile("cp.async.wait_group 0;");
    };

    // MMA phase for one group; returns partial c4 and joins via redbuf
    auto mma_phase = [&](unsigned adAh, unsigned adAl, float *c4) {
#pragma unroll
        for (int kk = 0; kk < 8; kk++) {
            const unsigned off = kk * 32;
            unsigned a0, a1, a2, a3, l0, l1, l2, l3, b0, b1, b2, b3;
            ldsm_x4(a0, a1, a2, a3, adAh + off);
            ldsm_x4(l0, l1, l2, l3, adAl + off);
            ldsm_x4(b0, b1, b2, b3, addrB + off);
            mma4(c4, a0, a1, a2, a3, b0, b1);
            mma4(c4, a0, a1, a2, a3, b2, b3);
            mma4(c4, l0, l1, l2, l3, b0, b1);
        }
        if (kq > 0) {
            float *dst = &redbuf[((kq - 1) * 2 + ntile) * 128 + lane * 4];
            dst[0] = c4[0]; dst[1] = c4[1]; dst[2] = c4[2]; dst[3] = c4[3];
        }
        __syncthreads();
    };

    // epilogue for one group (warps 0-1 only)
    auto epilogue = [&](float *c4, float2 xw0, float2 xw1, int m0, int m1,
                        unsigned *cnt, int t) {
        float v0 = c4[0], v1 = c4[1], v2 = c4[2], v3 = c4[3];
#pragma unroll
        for (int j = 0; j < 3; j++) {
            const float *src = &redbuf[(j * 2 + ntile) * 128 + lane * 4];
            v0 += src[0]; v1 += src[1]; v2 += src[2]; v3 += src[3];
        }
        v0 += xw0.x; v1 += xw0.y; v2 += xw1.x; v3 += xw1.y;
        float h0v = fast_tanh(v0), h1v = fast_tanh(v1);
        float h2v = fast_tanh(v2), h3v = fast_tanh(v3);

        const int wb = t & 1;
        __nv_bfloat16 hi, lo;
        __nv_bfloat162 ph, pl;
        split2(h0v, hi, lo); ph.x = hi; pl.x = lo;
        split2(h1v, hi, lo); ph.y = hi; pl.y = lo;
        *(unsigned *)&g_hh[wb][m0 * HH + ccol] = *(unsigned *)&ph;
        *(unsigned *)&g_hl[wb][m0 * HH + ccol] = *(unsigned *)&pl;
        split2(h2v, hi, lo); ph.x = hi; pl.x = lo;
        split2(h3v, hi, lo); ph.y = hi; pl.y = lo;
        *(unsigned *)&g_hh[wb][m1 * HH + ccol] = *(unsigned *)&ph;
        *(unsigned *)&g_hl[wb][m1 * HH + ccol] = *(unsigned *)&pl;

        asm volatile("bar.sync 1, 64;" ::: "memory");
        if (tid == 0 && t < TT - 1) {
            asm volatile("red.release.gpu.global.add.u32 [%0], %1;"
                         :: "l"(cnt), "r"(1u) : "memory");
        }
        *(float2 *)&out[((size_t)m0 * TT + t) * HH + ccol] = make_float2(h0v, h1v);
        *(float2 *)&out[((size_t)m1 * TT + t) * HH + ccol] = make_float2(h2v, h3v);
    };

    auto poll = [&](unsigned *cnt, unsigned target) {
        unsigned v;
        do {
            asm volatile("ld.acquire.gpu.global.u32 %0, [%1];"
                         : "=r"(v) : "l"(cnt) : "memory");
        } while (v < target);
    };

    // ---- prologue: stage A from buffer 1 (h0, pre-split by init kernel) ----
    {
        const __nv_bfloat16 *sH = g_hh[1] + (size_t)rbA * HH;
        const __nv_bfloat16 *sL = g_hl[1] + (size_t)rbA * HH;
        for (int c = tid; c < 2048; c += 256) {
            int bufsel = c >> 10, cc = c & 1023;
            int r = cc >> 6, col = (cc & 63) * 8;
            if (bufsel == 0) cp16(HhA + r * HSTRIDE + col, sH + r * HH + col);
            else             cp16(HlA + r * HSTRIDE + col, sL + r * HH + col);
        }
        asm volatile("cp.async.commit_group;");
        asm volatile("cp.async.wait_group 0;");
    }
    __syncthreads();

    for (int t = 0; t < TT; t++) {
        // prefetch xwx for both groups (kq0 warps)
        float2 xwA0, xwA1, xwB0, xwB1;
        if (kq == 0) {
            xwA0 = *(const float2 *)&out[((size_t)m0A * TT + t) * HH + ccol];
            xwA1 = *(const float2 *)&out[((size_t)m1A * TT + t) * HH + ccol];
            xwB0 = *(const float2 *)&out[((size_t)m0B * TT + t) * HH + ccol];
            xwB1 = *(const float2 *)&out[((size_t)m1B * TT + t) * HH + ccol];
        }

        // ---- phase A ----
        float c4[4] = {0.f, 0.f, 0.f, 0.f};
        mma_phase(adAhA, adAlA, c4);
        if (tid < 64) {
            epilogue(c4, xwA0, xwA1, m0A, m1A, cntA, t);
        } else {
            if (tid == 64) poll(cntB, (unsigned)(SUBS * t));
            asm volatile("bar.sync 2, 192;" ::: "memory");
            stage192(HhB, HlB, rbB, (t + 1) & 1);   // h_B(t-1) lives in buf (t-1)&1
        }
        __syncthreads();

        // ---- phase B ----
        c4[0] = c4[1] = c4[2] = c4[3] = 0.f;
        mma_phase(adAhB, adAlB, c4);
        if (tid < 64) {
            epilogue(c4, xwB0, xwB1, m0B, m1B, cntB, t);
        } else if (t < TT - 1) {
            if (tid == 64) poll(cntA, (unsigned)(SUBS * (t + 1)));
            asm volatile("bar.sync 2, 192;" ::: "memory");
            stage192(HhA, HlA, rbA, t & 1);         // h_A(t) just published
        }
        __syncthreads();
    }
}

// ---------------- launch ----------------------------------------------------
extern "C" void kernel_launch(void *const *d_in, const int *in_sizes, int n_in,
                              void *d_out, int out_size) {
    const float *x  = (const float *)d_in[0];   // (64, 512, 512)
    const float *h0 = (const float *)d_in[1];   // (64, 512)
    const float *Wx = (const float *)d_in[2];   // (512, 512)
    const float *Wh = (const float *)d_in[3];   // (512, 512)
    const float *b  = (const float *)d_in[4];   // (512,)
    float *out = (float *)d_out;                // (64, 512, 512)

    const int scan_smem = (6 * SCAN_NT * HSTRIDE) * (int)sizeof(__nv_bfloat16);
    cudaFuncSetAttribute(rnn_scan_kernel,
                         cudaFuncAttributeMaxDynamicSharedMemorySize, scan_smem);

    init_kernel<<<64, 128>>>(h0);
    dim3 grid1(NB * TT / 128, HH / 64);
    gemm_xwx_kernel<<<grid1, 256>>>(x, Wx, b, out);
    rnn_scan_kernel<<<SCAN_CTAS, 256, scan_smem>>>(Wh, out);
}

// round 9
// speedup vs baseline: 1.2136x; 1.2136x over previous
#include <cuda_runtime.h>
#include <cuda_bf16.h>

#define NB 64      // batch
#define TT 512     // timesteps
#define DD 512     // input size
#define HH 512     // hidden size

#define GROUPS 4           // m-groups (16 batch rows each) -- independent recurrences
#define SUBS 32            // n-CTAs per group
#define SCAN_CTAS (GROUPS * SUBS)   // 128
#define SCAN_NT 16         // hidden columns per CTA
#define MROWS 16           // batch rows per group
#define HSTRIDE 520        // 512 + 8 pad halves (16B-aligned rows, conflict-free LDSM)

// ---------------- scratch (device globals; no allocation allowed) ----------
// h in MMA A-fragment layout: [buf][group][ktile 0..31][lane 0..31][reg 0..3]
__device__ __align__(16) unsigned g_fh[2][GROUPS][32][32][4];   // hi
__device__ __align__(16) unsigned g_fl[2][GROUPS][32][32][4];   // lo
__device__ __align__(128) unsigned g_cnt[GROUPS * 32];          // arrival counters

// ---------------- helpers --------------------------------------------------
__device__ __forceinline__ void split2(float v, __nv_bfloat16 &hi, __nv_bfloat16 &lo) {
    hi = __float2bfloat16(v);
    lo = __float2bfloat16(v - __bfloat162float(hi));
}

__device__ __forceinline__ void mma4(float *c, unsigned a0, unsigned a1, unsigned a2,
                                     unsigned a3, unsigned b0, unsigned b1) {
    asm volatile(
        "mma.sync.aligned.m16n8k16.row.col.f32.bf16.bf16.f32 "
        "{%0,%1,%2,%3}, {%4,%5,%6,%7}, {%8,%9}, {%0,%1,%2,%3};\n"
        : "+f"(c[0]), "+f"(c[1]), "+f"(c[2]), "+f"(c[3])
        : "r"(a0), "r"(a1), "r"(a2), "r"(a3), "r"(b0), "r"(b1));
}

__device__ __forceinline__ void ldsm_x4(unsigned &r0, unsigned &r1, unsigned &r2,
                                        unsigned &r3, unsigned addr) {
    asm volatile("ldmatrix.sync.aligned.m8n8.x4.shared.b16 {%0,%1,%2,%3}, [%4];"
                 : "=r"(r0), "=r"(r1), "=r"(r2), "=r"(r3)
                 : "r"(addr));
}

__device__ __forceinline__ float fast_tanh(float x) {
    float e = __expf(2.0f * x);
    return 1.0f - __fdividef(2.0f, e + 1.0f);
}

__device__ __forceinline__ unsigned pack2(__nv_bfloat16 a, __nv_bfloat16 b) {
    __nv_bfloat162 p = {a, b};
    return *(unsigned *)&p;
}

// ---------------- kernel 1: xWx = x @ Wx + b  -> out (R5 version) ----------
__global__ __launch_bounds__(256) void gemm_xwx_kernel(
    const float *__restrict__ x, const float *__restrict__ Wx,
    const float *__restrict__ b, float *__restrict__ out) {

    __shared__ __align__(16) __nv_bfloat16 Ah[128 * 40];
    __shared__ __align__(16) __nv_bfloat16 Al[128 * 40];
    __shared__ __align__(16) __nv_bfloat16 Bh[64 * 40];
    __shared__ __align__(16) __nv_bfloat16 Bl[64 * 40];

    const int tid  = threadIdx.x;
    const int warp = tid >> 5;
    const int lane = tid & 31;
    const int g    = lane >> 2;
    const int tg   = lane & 3;
    const int wm   = warp >> 1;
    const int wn   = warp & 1;
    const int row0 = blockIdx.x * 128;
    const int col0 = blockIdx.y * 64;

    const int quad = lane >> 3, lrow = lane & 7;
    unsigned aHaddr[2], aLaddr[2], bAddr[4];
#pragma unroll
    for (int mt = 0; mt < 2; mt++) {
        int r = wm * 32 + mt * 16 + (quad & 1) * 8 + lrow;
        int off = r * 40 + (quad >> 1) * 8;
        aHaddr[mt] = (unsigned)__cvta_generic_to_shared(Ah + off);
        aLaddr[mt] = (unsigned)__cvta_generic_to_shared(Al + off);
    }
#pragma unroll
    for (int nt = 0; nt < 4; nt++) {
        int r = wn * 32 + nt * 8 + lrow;
        const __nv_bfloat16 *base = (quad < 2) ? Bh : Bl;
        bAddr[nt] = (unsigned)__cvta_generic_to_shared(base + r * 40 + (quad & 1) * 8);
    }

    float acc[2][4][4];
#pragma unroll
    for (int mt = 0; mt < 2; mt++)
#pragma unroll
        for (int nt = 0; nt < 4; nt++)
#pragma unroll
            for (int i = 0; i < 4; i++) acc[mt][nt][i] = 0.0f;

    for (int k0 = 0; k0 < DD; k0 += 32) {
        __syncthreads();
#pragma unroll
        for (int i = 0; i < 16; i++) {
            int idx = tid + i * 256;
            int r = idx >> 5, c = idx & 31;
            float v = x[(size_t)(row0 + r) * DD + k0 + c];
            __nv_bfloat16 hi, lo; split2(v, hi, lo);
            Ah[r * 40 + c] = hi; Al[r * 40 + c] = lo;
        }
#pragma unroll
        for (int i = 0; i < 8; i++) {
            int idx = tid + i * 256;
            int nn = idx & 63, kk = idx >> 6;
            float v = Wx[(size_t)(k0 + kk) * HH + col0 + nn];
            __nv_bfloat16 hi, lo; split2(v, hi, lo);
            Bh[nn * 40 + kk] = hi; Bl[nn * 40 + kk] = lo;
        }
        __syncthreads();

#pragma unroll
        for (int ks = 0; ks < 2; ks++) {
            const unsigned off = ks * 32;
            unsigned bfr[4][4];
#pragma unroll
            for (int nt = 0; nt < 4; nt++)
                ldsm_x4(bfr[nt][0], bfr[nt][1], bfr[nt][2], bfr[nt][3], bAddr[nt] + off);
#pragma unroll
            for (int mt = 0; mt < 2; mt++) {
                unsigned a0, a1, a2, a3, l0, l1, l2, l3;
                ldsm_x4(a0, a1, a2, a3, aHaddr[mt] + off);
                ldsm_x4(l0, l1, l2, l3, aLaddr[mt] + off);
#pragma unroll
                for (int nt = 0; nt < 4; nt++) {
                    mma4(acc[mt][nt], a0, a1, a2, a3, bfr[nt][0], bfr[nt][1]);
                    mma4(acc[mt][nt], a0, a1, a2, a3, bfr[nt][2], bfr[nt][3]);
                    mma4(acc[mt][nt], l0, l1, l2, l3, bfr[nt][0], bfr[nt][1]);
                }
            }
        }
    }

#pragma unroll
    for (int mt = 0; mt < 2; mt++)
#pragma unroll
        for (int nt = 0; nt < 4; nt++) {
            int r = row0 + wm * 32 + mt * 16 + g;
            int c = col0 + wn * 32 + nt * 8 + tg * 2;
            float b0 = b[c], b1 = b[c + 1];
            out[(size_t)r * HH + c]           = acc[mt][nt][0] + b0;
            out[(size_t)r * HH + c + 1]       = acc[mt][nt][1] + b1;
            out[(size_t)(r + 8) * HH + c]     = acc[mt][nt][2] + b0;
            out[(size_t)(r + 8) * HH + c + 1] = acc[mt][nt][3] + b1;
        }
}

// ---------------- init: reset counters + h0 -> fragment buffer 1 -----------
__global__ __launch_bounds__(256) void init_kernel(const float *__restrict__ h0) {
    const int idx = blockIdx.x * 256 + threadIdx.x;   // 16384 threads
    const int reg   = idx & 3;
    const int lane  = (idx >> 2) & 31;
    const int tile  = (idx >> 7) & 31;
    const int group = idx >> 12;
    const int ntile = reg >> 1, rh = reg & 1;
    const int row = rh * 8 + (lane >> 2);
    const int col = tile * 16 + ntile * 8 + (lane & 3) * 2;
    const int m = group * MROWS + row;
    float v0 = h0[(size_t)m * HH + col];
    float v1 = h0[(size_t)m * HH + col + 1];
    __nv_bfloat16 h0h, h0l, h1h, h1l;
    split2(v0, h0h, h0l); split2(v1, h1h, h1l);
    g_fh[1][group][tile][lane][reg] = pack2(h0h, h1h);
    g_fl[1][group][tile][lane][reg] = pack2(h0l, h1l);
    if (idx < GROUPS * 32) g_cnt[idx] = 0;
}

// ---------------- kernel 2: persistent recurrent scan -----------------------
// 128 CTAs = 4 groups x 32 subs (16 cols each). 8 warps = 8 K-eighths (K=64),
// each covering the full n16. h exchanged in MMA fragment layout via L2
// (__ldcg), no SMEM staging. Distributed 128-thread epilogue writes fragments
// back at [lane][warp] directly.
__global__ __launch_bounds__(256) void rnn_scan_kernel(
    const float *__restrict__ Wh, float *__restrict__ out) {

    extern __shared__ __nv_bfloat16 smem[];
    __nv_bfloat16 *Wsh = smem;                        // 16 x 520
    __nv_bfloat16 *Wsl = Wsh + SCAN_NT * HSTRIDE;     // 16 x 520
    __shared__ float redbuf[2][8][16][18];            // [buf][warp][row][col(pad)]

    const int tid   = threadIdx.x;
    const int warp  = tid >> 5;       // K-eighth 0..7
    const int lane  = tid & 31;
    const int g     = lane >> 2;
    const int tg    = lane & 3;
    const int group = blockIdx.x >> 5;
    const int sub   = blockIdx.x & 31;
    const int cb    = sub * SCAN_NT;
    const int rbase = group * MROWS;

    unsigned *cntp = &g_cnt[group * 32];

    // resident Wh slice: Wsh[n][k] = Wh[k][cb+n], split hi/lo
    for (int idx = tid; idx < HH * SCAN_NT; idx += 256) {
        int n = idx & (SCAN_NT - 1), k = idx >> 4;
        float v = Wh[(size_t)k * HH + cb + n];
        __nv_bfloat16 hi, lo; split2(v, hi, lo);
        Wsh[n * HSTRIDE + k] = hi; Wsl[n * HSTRIDE + k] = lo;
    }

    // B ldmatrix addresses for both n8 tiles (quad trick: hi in b0b1, lo in b2b3)
    const int quad = lane >> 3, lrow = lane & 7;
    const __nv_bfloat16 *bbase = (quad < 2) ? Wsh : Wsl;
    const unsigned adB0 = (unsigned)__cvta_generic_to_shared(
        bbase + lrow * HSTRIDE + (quad & 1) * 8);
    const unsigned adB1 = (unsigned)__cvta_generic_to_shared(
        bbase + (8 + lrow) * HSTRIDE + (quad & 1) * 8);

    // epilogue mapping (threads 0-127): value (row, col..col+1), frag reg = warp
    const int ew = warp;              // 0..3 used
    const int entile = ew >> 1, erh = ew & 1;
    const int erow = erh * 8 + g;
    const int ecol = entile * 8 + tg * 2;
    const size_t out_base = ((size_t)(rbase + erow) * TT) * HH + cb + ecol;

    __syncthreads();

    for (int t = 0; t < TT; t++) {
        const int tb = t & 1;          // write buffer
        const int rb = tb ^ 1;         // read buffer (holds h_{t-1})

        // ---- prefetch xwx (epilogue threads) ----
        float2 xw;
        if (tid < 128) xw = *(const float2 *)&out[out_base + (size_t)t * HH];

        // ---- wait for producers of h_{t-1} ----
        if (t > 0) {
            if (tid == 0) {
                const unsigned target = (unsigned)(SUBS * t);
                unsigned v;
                do {
                    asm volatile("ld.acquire.gpu.global.u32 %0, [%1];"
                                 : "=r"(v) : "l"(cntp) : "memory");
                } while (v < target);
            }
        }
        __syncthreads();

        // ---- k-loop: 4 k-tiles per warp, A-frags via direct L2 LDG ----
        float c4a[4] = {0.f, 0.f, 0.f, 0.f};
        float c4b[4] = {0.f, 0.f, 0.f, 0.f};
#pragma unroll
        for (int kk = 0; kk < 4; kk++) {
            const int tile = warp * 4 + kk;
            uint4 ah = __ldcg((const uint4 *)&g_fh[rb][group][tile][lane][0]);
            uint4 al = __ldcg((const uint4 *)&g_fl[rb][group][tile][lane][0]);
            unsigned b0, b1, b2, b3, d0, d1, d2, d3;
            ldsm_x4(b0, b1, b2, b3, adB0 + tile * 32);
            ldsm_x4(d0, d1, d2, d3, adB1 + tile * 32);
            mma4(c4a, ah.x, ah.y, ah.z, ah.w, b0, b1);   // Ah*Bh n0-7
            mma4(c4a, ah.x, ah.y, ah.z, ah.w, b2, b3);   // Ah*Bl
            mma4(c4a, al.x, al.y, al.z, al.w, b0, b1);   // Al*Bh
            mma4(c4b, ah.x, ah.y, ah.z, ah.w, d0, d1);   // n8-15
            mma4(c4b, ah.x, ah.y, ah.z, ah.w, d2, d3);
            mma4(c4b, al.x, al.y, al.z, al.w, d0, d1);
        }

        // ---- write partials to (double-buffered) redbuf ----
        *(float2 *)&redbuf[tb][warp][g][tg * 2]         = make_float2(c4a[0], c4a[1]);
        *(float2 *)&redbuf[tb][warp][g + 8][tg * 2]     = make_float2(c4a[2], c4a[3]);
        *(float2 *)&redbuf[tb][warp][g][8 + tg * 2]     = make_float2(c4b[0], c4b[1]);
        *(float2 *)&redbuf[tb][warp][g + 8][8 + tg * 2] = make_float2(c4b[2], c4b[3]);
        __syncthreads();

        // ---- distributed epilogue (threads 0-127) ----
        if (tid < 128) {
            float v0 = xw.x, v1 = xw.y;
#pragma unroll
            for (int p = 0; p < 8; p++) {
                float2 pr = *(const float2 *)&redbuf[tb][p][erow][ecol];
                v0 += pr.x; v1 += pr.y;
            }
            float h0v = fast_tanh(v0), h1v = fast_tanh(v1);

            // publish fragments (release set)
            __nv_bfloat16 hh0, hl0, hh1, hl1;
            split2(h0v, hh0, hl0); split2(h1v, hh1, hl1);
            g_fh[tb][group][sub][lane][ew] = pack2(hh0, hh1);
            g_fl[tb][group][sub][lane][ew] = pack2(hl0, hl1);

            asm volatile("bar.sync 1, 128;" ::: "memory");
            if (tid == 0 && t < TT - 1) {
                asm volatile("red.release.gpu.global.add.u32 [%0], %1;"
                             :: "l"(cntp), "r"(1u) : "memory");
            }

            // fp32 outputs off the release path
            *(float2 *)&out[out_base + (size_t)t * HH] = make_float2(h0v, h1v);
        }
    }
}

// ---------------- launch ----------------------------------------------------
extern "C" void kernel_launch(void *const *d_in, const int *in_sizes, int n_in,
                              void *d_out, int out_size) {
    const float *x  = (const float *)d_in[0];   // (64, 512, 512)
    const float *h0 = (const float *)d_in[1];   // (64, 512)
    const float *Wx = (const float *)d_in[2];   // (512, 512)
    const float *Wh = (const float *)d_in[3];   // (512, 512)
    const float *b  = (const float *)d_in[4];   // (512,)
    float *out = (float *)d_out;                // (64, 512, 512)

    const int scan_smem = (2 * SCAN_NT * HSTRIDE) * (int)sizeof(__nv_bfloat16);
    cudaFuncSetAttribute(rnn_scan_kernel,
                         cudaFuncAttributeMaxDynamicSharedMemorySize, scan_smem);

    init_kernel<<<64, 256>>>(h0);
    dim3 grid1(NB * TT / 128, HH / 64);
    gemm_xwx_kernel<<<grid1, 256>>>(x, Wx, b, out);
    rnn_scan_kernel<<<SCAN_CTAS, 256, scan_smem>>>(Wh, out);
}